// round 4
// baseline (speedup 1.0000x reference)
#include <cuda_runtime.h>

#define NN 500000
#define BB 4096
#define DD 256
#define DL 10
#define TH 768

// ---------------- device scratch (no allocation allowed) ----------------
__device__ int   d_segstart[BB + 1];
__device__ float d_c1[BB * DL];          // graph-half of layer1 + b_l1, per graph
__device__ float d_Sdiv[BB * DD];        // softmax-weighted mean of node feats per graph
__device__ float d_has[BB];              // 1 if segment nonempty else 0
__device__ float d_Wcomb[TH * DD];       // W_ih @ W_msg
__device__ float d_bmsgih[TH];           // W_ih @ b_msg
__device__ float d_gi[(size_t)BB * TH];
__device__ float d_gh[(size_t)BB * TH];

// ---------------- K1: segment boundaries (ids are sorted, int32!) ----------------
__global__ void k_segstart(const int* __restrict__ seg) {
    int g = blockIdx.x * blockDim.x + threadIdx.x;
    if (g > BB) return;
    int lo = 0, hi = NN;
    while (lo < hi) {
        int mid = (lo + hi) >> 1;
        if (seg[mid] < g) lo = mid + 1; else hi = mid;
    }
    d_segstart[g] = lo;
}

// ---------------- K2: c1[g][j] = W_l1[j, :256] . relu(gf[g]) + b_l1[j] ----------------
__global__ void k_c1(const float* __restrict__ gf, const float* __restrict__ Wl1,
                     const float* __restrict__ bl1) {
    __shared__ float sc[DL];
    int g = blockIdx.x, t = threadIdx.x;
    if (t < DL) sc[t] = bl1[t];
    __syncthreads();
    float gv = fmaxf(gf[g * DD + t], 0.f);
#pragma unroll
    for (int j = 0; j < DL; j++) atomicAdd(&sc[j], Wl1[j * (2 * DD) + t] * gv);
    __syncthreads();
    if (t < DL) d_c1[g * DL + t] = sc[t];
}

// ---------------- K3: W_comb = W_ih @ W_msg  (768x256) ----------------
__global__ void k_wcomb(const float* __restrict__ Wih, const float* __restrict__ Wmsg) {
    __shared__ float wih_s[4][DD];
    int o0 = blockIdx.x * 4, t = threadIdx.x;
#pragma unroll
    for (int oo = 0; oo < 4; oo++) wih_s[oo][t] = Wih[(o0 + oo) * DD + t];
    __syncthreads();
    float a0 = 0.f, a1 = 0.f, a2 = 0.f, a3 = 0.f;
    for (int m = 0; m < DD; m++) {
        float wm = Wmsg[m * DD + t];
        a0 = fmaf(wih_s[0][m], wm, a0);
        a1 = fmaf(wih_s[1][m], wm, a1);
        a2 = fmaf(wih_s[2][m], wm, a2);
        a3 = fmaf(wih_s[3][m], wm, a3);
    }
    d_Wcomb[(o0 + 0) * DD + t] = a0;
    d_Wcomb[(o0 + 1) * DD + t] = a1;
    d_Wcomb[(o0 + 2) * DD + t] = a2;
    d_Wcomb[(o0 + 3) * DD + t] = a3;
}

// ---------------- K3b: bmsg_ih[o] = W_ih[o] . b_msg ----------------
__global__ void k_bmsgih(const float* __restrict__ Wih, const float* __restrict__ bmsg) {
    __shared__ float s;
    int o = blockIdx.x, t = threadIdx.x;
    if (t == 0) s = 0.f;
    __syncthreads();
    float v = Wih[o * DD + t] * bmsg[t];
#pragma unroll
    for (int off = 16; off; off >>= 1) v += __shfl_xor_sync(0xffffffffu, v, off);
    if ((t & 31) == 0) atomicAdd(&s, v);
    __syncthreads();
    if (t == 0) d_bmsgih[o] = s;
}

// ---------------- K4: fused attention + weighted segment mean ----------------
// One BLOCK (4 warps) per graph; nodes interleaved stride-4 across warps.
// Lane owns 8 features: {4*lane..4*lane+3, 128+4*lane..+3}.
// W_l1 node-half in registers (80/lane). Depth-4 register-ring prefetch per warp.
__global__ void __launch_bounds__(128) k_attn(const float* __restrict__ xf,
                                              const float* __restrict__ Wl1,
                                              const float* __restrict__ Wl2,
                                              const float* __restrict__ bl2) {
    __shared__ float c_s[DL];
    __shared__ float w2_s[DL];
    __shared__ float s_Z[4];
    __shared__ float4 s_acc[4][64];   // [warp][feature-float4]
    int tid = threadIdx.x;
    int wo = tid >> 5, lane = tid & 31;
    int g = blockIdx.x;
    if (tid < DL) c_s[tid] = d_c1[g * DL + tid];
    if (tid >= 32 && tid < 32 + DL) w2_s[tid - 32] = Wl2[tid - 32];
    __syncthreads();

    float W[DL][8];
#pragma unroll
    for (int j = 0; j < DL; j++) {
        const float* wr = Wl1 + j * (2 * DD) + DD;   // node half: columns 256..511
        float4 a = *(const float4*)(wr + lane * 4);
        float4 b = *(const float4*)(wr + 128 + lane * 4);
        W[j][0] = a.x; W[j][1] = a.y; W[j][2] = a.z; W[j][3] = a.w;
        W[j][4] = b.x; W[j][5] = b.y; W[j][6] = b.z; W[j][7] = b.w;
    }
    float b2v = bl2[0];
    float c1r[DL], w2r[DL];
#pragma unroll
    for (int j = 0; j < DL; j++) { c1r[j] = c_s[j]; w2r[j] = w2_s[j]; }

    int i0 = d_segstart[g], i1 = d_segstart[g + 1];
    int myi = i0 + wo;                 // this warp's first node; stride 4

    float acc0 = 0.f, acc1 = 0.f, acc2 = 0.f, acc3 = 0.f;
    float acc4 = 0.f, acc5 = 0.f, acc6 = 0.f, acc7 = 0.f;
    float Z = 0.f;

    // depth-4 prefetch ring
    float4 ra0, rb0, ra1, rb1, ra2, rb2, ra3, rb3;
    int q = myi;
#define LDNODE(A, B, IDX) do { const float4* rp = (const float4*)(xf + (size_t)(IDX) * DD); \
        (A) = rp[lane]; (B) = rp[32 + lane]; } while (0)
    if (q < i1) { LDNODE(ra0, rb0, q); } q += 4;
    if (q < i1) { LDNODE(ra1, rb1, q); } q += 4;
    if (q < i1) { LDNODE(ra2, rb2, q); } q += 4;
    if (q < i1) { LDNODE(ra3, rb3, q); } q += 4;

    auto process = [&](float4 a, float4 b) {
        float x0 = a.x, x1 = a.y, x2 = a.z, x3 = a.w;
        float x4 = b.x, x5 = b.y, x6 = b.z, x7 = b.w;
        float p[DL];
#pragma unroll
        for (int j = 0; j < DL; j++) {
            float s = W[j][0] * x0;
            s = fmaf(W[j][1], x1, s);
            s = fmaf(W[j][2], x2, s);
            s = fmaf(W[j][3], x3, s);
            s = fmaf(W[j][4], x4, s);
            s = fmaf(W[j][5], x5, s);
            s = fmaf(W[j][6], x6, s);
            s = fmaf(W[j][7], x7, s);
            p[j] = s;
        }
#pragma unroll
        for (int off = 16; off; off >>= 1) {
#pragma unroll
            for (int j = 0; j < DL; j++) p[j] += __shfl_xor_sync(0xffffffffu, p[j], off);
        }
        float lg = b2v;
#pragma unroll
        for (int j = 0; j < DL; j++) {
            float h = c1r[j] + p[j];
            h = (h > 0.f) ? h : 0.01f * h;
            lg = fmaf(w2r[j], h, lg);
        }
        lg = (lg > 0.f) ? lg : 0.01f * lg;
        float w = __expf(lg);     // logits are O(0.2): no max-subtraction needed
        Z += w;
        acc0 = fmaf(w, x0, acc0); acc1 = fmaf(w, x1, acc1);
        acc2 = fmaf(w, x2, acc2); acc3 = fmaf(w, x3, acc3);
        acc4 = fmaf(w, x4, acc4); acc5 = fmaf(w, x5, acc5);
        acc6 = fmaf(w, x6, acc6); acc7 = fmaf(w, x7, acc7);
    };

    for (int i = myi; i < i1; i += 16) {
        process(ra0, rb0);
        if (q < i1) { LDNODE(ra0, rb0, q); } q += 4;
        if (i + 4 < i1) {
            process(ra1, rb1);
            if (q < i1) { LDNODE(ra1, rb1, q); } q += 4;
            if (i + 8 < i1) {
                process(ra2, rb2);
                if (q < i1) { LDNODE(ra2, rb2, q); } q += 4;
                if (i + 12 < i1) {
                    process(ra3, rb3);
                    if (q < i1) { LDNODE(ra3, rb3, q); } q += 4;
                }
            }
        }
    }
#undef LDNODE

    // combine 4 warps
    if (lane == 0) s_Z[wo] = Z;
    s_acc[wo][lane]      = make_float4(acc0, acc1, acc2, acc3);
    s_acc[wo][32 + lane] = make_float4(acc4, acc5, acc6, acc7);
    __syncthreads();
    if (tid < 64) {
        float Zt = s_Z[0] + s_Z[1] + s_Z[2] + s_Z[3];
        float invZ = (i1 > i0) ? (1.f / Zt) : 0.f;
        float4 v0 = s_acc[0][tid], v1 = s_acc[1][tid], v2 = s_acc[2][tid], v3 = s_acc[3][tid];
        float4 o;
        o.x = (v0.x + v1.x + v2.x + v3.x) * invZ;
        o.y = (v0.y + v1.y + v2.y + v3.y) * invZ;
        o.z = (v0.z + v1.z + v2.z + v3.z) * invZ;
        o.w = (v0.w + v1.w + v2.w + v3.w) * invZ;
        ((float4*)(d_Sdiv + (size_t)g * DD))[tid] = o;
        if (tid == 0) d_has[g] = (i1 > i0) ? 1.f : 0.f;
    }
}

// ---------------- K5: SGEMM  C[4096x768] = A[4096x256] * B[768x256]^T + bias ----------------
// mode 0: A=d_Sdiv, B=d_Wcomb, C=d_gi, bias = b_ih + has[m]*bmsg_ih
// mode 1: A=graph_feats, B=W_hh,  C=d_gh, bias = b_hh
__global__ void __launch_bounds__(256) k_gemm(int mode, const float* __restrict__ Aparam,
                                              const float* __restrict__ Bparam,
                                              const float* __restrict__ bias) {
    const float* A  = mode ? Aparam : d_Sdiv;
    const float* Bw = mode ? Bparam : d_Wcomb;
    float* C = mode ? d_gh : d_gi;

    __shared__ float As[8][128];
    __shared__ float Bs[8][64];
    int bm = blockIdx.y * 128, bn = blockIdx.x * 64;
    int tid = threadIdx.x;
    int alr = tid >> 1, alc = (tid & 1) * 4;  // A tile: 128 rows x 8 k
    int tx = tid & 15, ty = tid >> 4;         // thread tile 8x4

    float accv[8][4];
#pragma unroll
    for (int i = 0; i < 8; i++)
#pragma unroll
        for (int j = 0; j < 4; j++) accv[i][j] = 0.f;

    float4 av = *(const float4*)(A + (size_t)(bm + alr) * DD + alc);
    float4 bv;
    if (tid < 128) bv = *(const float4*)(Bw + (size_t)(bn + alr) * DD + alc);

    for (int k0 = 0; k0 < DD; k0 += 8) {
        As[alc + 0][alr] = av.x; As[alc + 1][alr] = av.y;
        As[alc + 2][alr] = av.z; As[alc + 3][alr] = av.w;
        if (tid < 128) {
            Bs[alc + 0][alr] = bv.x; Bs[alc + 1][alr] = bv.y;
            Bs[alc + 2][alr] = bv.z; Bs[alc + 3][alr] = bv.w;
        }
        __syncthreads();
        if (k0 + 8 < DD) {  // prefetch next K-slab over the compute
            av = *(const float4*)(A + (size_t)(bm + alr) * DD + k0 + 8 + alc);
            if (tid < 128) bv = *(const float4*)(Bw + (size_t)(bn + alr) * DD + k0 + 8 + alc);
        }
#pragma unroll
        for (int k = 0; k < 8; k++) {
            float ar[8], br[4];
            *(float4*)(ar)     = *(const float4*)&As[k][ty * 4];
            *(float4*)(ar + 4) = *(const float4*)&As[k][64 + ty * 4];
            *(float4*)(br)     = *(const float4*)&Bs[k][tx * 4];
#pragma unroll
            for (int i = 0; i < 8; i++)
#pragma unroll
                for (int j = 0; j < 4; j++) accv[i][j] = fmaf(ar[i], br[j], accv[i][j]);
        }
        __syncthreads();
    }

    int n0 = bn + tx * 4;
#pragma unroll
    for (int i = 0; i < 8; i++) {
        int m = bm + ((i < 4) ? (ty * 4 + i) : (64 + ty * 4 + (i - 4)));
        float hv = mode ? 0.f : d_has[m];
        float4 o;
        o.x = accv[i][0] + bias[n0 + 0] + (mode ? 0.f : hv * d_bmsgih[n0 + 0]);
        o.y = accv[i][1] + bias[n0 + 1] + (mode ? 0.f : hv * d_bmsgih[n0 + 1]);
        o.z = accv[i][2] + bias[n0 + 2] + (mode ? 0.f : hv * d_bmsgih[n0 + 2]);
        o.w = accv[i][3] + bias[n0 + 3] + (mode ? 0.f : hv * d_bmsgih[n0 + 3]);
        *(float4*)(C + (size_t)m * TH + n0) = o;
    }
}

// ---------------- K6: GRU gate combine ----------------
__global__ void k_gates(const float* __restrict__ gf, float* __restrict__ out) {
    int idx = blockIdx.x * blockDim.x + threadIdx.x;   // over BB*DD
    int g = idx >> 8, f = idx & 255;
    const float* gi = d_gi + (size_t)g * TH;
    const float* gh = d_gh + (size_t)g * TH;
    float ir = gi[f], iz = gi[DD + f], in_ = gi[2 * DD + f];
    float hr = gh[f], hz = gh[DD + f], hn = gh[2 * DD + f];
    float r = 1.f / (1.f + __expf(-(ir + hr)));
    float z = 1.f / (1.f + __expf(-(iz + hz)));
    float n = tanhf(in_ + r * hn);
    out[idx] = (1.f - z) * n + z * gf[idx];
}

// ---------------- launch ----------------
extern "C" void kernel_launch(void* const* d_in, const int* in_sizes, int n_in,
                              void* d_out, int out_size) {
    const float* node = (const float*)d_in[0];
    const float* gf   = (const float*)d_in[1];
    const int*   seg  = (const int*)d_in[2];     // JAX coerces int64 -> int32 (x64 disabled)
    const float* Wmsg = (const float*)d_in[3];
    const float* bmsg = (const float*)d_in[4];
    const float* Wl1  = (const float*)d_in[5];
    const float* bl1  = (const float*)d_in[6];
    const float* Wl2  = (const float*)d_in[7];
    const float* bl2  = (const float*)d_in[8];
    const float* Wih  = (const float*)d_in[9];
    const float* Whh  = (const float*)d_in[10];
    const float* bih  = (const float*)d_in[11];
    const float* bhh  = (const float*)d_in[12];
    float* out = (float*)d_out;

    k_segstart<<<(BB + 1 + 255) / 256, 256>>>(seg);
    k_c1<<<BB, 256>>>(gf, Wl1, bl1);
    k_wcomb<<<TH / 4, 256>>>(Wih, Wmsg);
    k_bmsgih<<<TH, 256>>>(Wih, bmsg);
    k_attn<<<BB, 128>>>(node, Wl1, Wl2, bl2);
    dim3 gg(TH / 64, BB / 128);
    k_gemm<<<gg, 256>>>(0, nullptr, nullptr, bih);
    k_gemm<<<gg, 256>>>(1, gf, Whh, bhh);
    k_gates<<<(BB * DD) / 256, 256>>>(gf, out);
}

// round 5
// speedup vs baseline: 1.0401x; 1.0401x over previous
#include <cuda_runtime.h>

#define NN 500000
#define BB 4096
#define DD 256
#define DL 10
#define TH 768

// ---------------- device scratch (no allocation allowed) ----------------
__device__ int   d_segstart[BB + 1];
__device__ float d_c1[BB * DL];          // graph-half of layer1 + b_l1, per graph
__device__ float d_Sdiv[BB * DD];        // softmax-weighted mean of node feats per graph
__device__ float d_has[BB];              // 1 if segment nonempty else 0
__device__ float d_Wcomb[TH * DD];       // W_ih @ W_msg
__device__ float d_bmsgih[TH];           // W_ih @ b_msg
__device__ float d_gi[(size_t)BB * TH];
__device__ float d_gh[(size_t)BB * TH];

// ---------------- K1: segment boundaries (ids are sorted, int32) ----------------
__global__ void k_segstart(const int* __restrict__ seg) {
    int g = blockIdx.x * blockDim.x + threadIdx.x;
    if (g > BB) return;
    int lo = 0, hi = NN;
    while (lo < hi) {
        int mid = (lo + hi) >> 1;
        if (seg[mid] < g) lo = mid + 1; else hi = mid;
    }
    d_segstart[g] = lo;
}

// ---------------- K2: c1[g][j] = W_l1[j, :256] . relu(gf[g]) + b_l1[j] ----------------
__global__ void k_c1(const float* __restrict__ gf, const float* __restrict__ Wl1,
                     const float* __restrict__ bl1) {
    __shared__ float sc[DL];
    int g = blockIdx.x, t = threadIdx.x;
    if (t < DL) sc[t] = bl1[t];
    __syncthreads();
    float gv = fmaxf(gf[g * DD + t], 0.f);
#pragma unroll
    for (int j = 0; j < DL; j++) atomicAdd(&sc[j], Wl1[j * (2 * DD) + t] * gv);
    __syncthreads();
    if (t < DL) d_c1[g * DL + t] = sc[t];
}

// ---------------- K3: W_comb = W_ih @ W_msg  (768x256) ----------------
__global__ void k_wcomb(const float* __restrict__ Wih, const float* __restrict__ Wmsg) {
    __shared__ float wih_s[4][DD];
    int o0 = blockIdx.x * 4, t = threadIdx.x;
#pragma unroll
    for (int oo = 0; oo < 4; oo++) wih_s[oo][t] = Wih[(o0 + oo) * DD + t];
    __syncthreads();
    float a0 = 0.f, a1 = 0.f, a2 = 0.f, a3 = 0.f;
    for (int m = 0; m < DD; m++) {
        float wm = Wmsg[m * DD + t];
        a0 = fmaf(wih_s[0][m], wm, a0);
        a1 = fmaf(wih_s[1][m], wm, a1);
        a2 = fmaf(wih_s[2][m], wm, a2);
        a3 = fmaf(wih_s[3][m], wm, a3);
    }
    d_Wcomb[(o0 + 0) * DD + t] = a0;
    d_Wcomb[(o0 + 1) * DD + t] = a1;
    d_Wcomb[(o0 + 2) * DD + t] = a2;
    d_Wcomb[(o0 + 3) * DD + t] = a3;
}

// ---------------- K3b: bmsg_ih[o] = W_ih[o] . b_msg ----------------
__global__ void k_bmsgih(const float* __restrict__ Wih, const float* __restrict__ bmsg) {
    __shared__ float s;
    int o = blockIdx.x, t = threadIdx.x;
    if (t == 0) s = 0.f;
    __syncthreads();
    float v = Wih[o * DD + t] * bmsg[t];
#pragma unroll
    for (int off = 16; off; off >>= 1) v += __shfl_xor_sync(0xffffffffu, v, off);
    if ((t & 31) == 0) atomicAdd(&s, v);
    __syncthreads();
    if (t == 0) d_bmsgih[o] = s;
}

// ---------------- K4: fused attention + weighted segment mean ----------------
// Block = 4 warps = 1 graph. Warp processes GROUPS of 4 nodes (stride 16).
// Lane owns 8 features per node. Butterfly reduction batched over 4 nodes:
//   xor16 per node -> select A|B, C|D -> xor8 -> select -> xor 4,2,1
// => 23.5 SHFL/node (vs 50), exp/logit-dot once per lane per 4 nodes.
// W_l1 node-half lives in shared (padded row 260, conflict-free), amortized
// across the 4 nodes: 5 LDS/node.
__global__ void __launch_bounds__(128) k_attn(const float* __restrict__ xf,
                                              const float* __restrict__ Wl1,
                                              const float* __restrict__ Wl2,
                                              const float* __restrict__ bl2) {
    __shared__ float Ws[DL][260];     // node-half of W_l1 (10x256, padded)
    __shared__ float c_s[DL];
    __shared__ float w2_s[DL];
    __shared__ float s_Z[4];
    __shared__ float4 s_acc[4][64];   // [warp][feature-float4]
    int tid = threadIdx.x;
    int wo = tid >> 5, lane = tid & 31;
    int g = blockIdx.x;

    for (int i = tid; i < DL * DD; i += 128) {
        int j = i >> 8, f = i & 255;
        Ws[j][f] = Wl1[j * (2 * DD) + DD + f];
    }
    if (tid < DL) { c_s[tid] = d_c1[g * DL + tid]; w2_s[tid] = Wl2[tid]; }
    __syncthreads();

    float c1r[DL], w2r[DL];
#pragma unroll
    for (int j = 0; j < DL; j++) { c1r[j] = c_s[j]; w2r[j] = w2_s[j]; }
    float b2v = bl2[0];

    int i0 = d_segstart[g], i1 = d_segstart[g + 1];

    float acc0 = 0.f, acc1 = 0.f, acc2 = 0.f, acc3 = 0.f;
    float acc4 = 0.f, acc5 = 0.f, acc6 = 0.f, acc7 = 0.f;
    float Z = 0.f;
    int nsel = ((lane >> 3) & 1) * 2 + ((lane >> 4) & 1);  // 0..7->0(A) 16..23->1(B) 8..15->2(C) 24..31->3(D)

    float4 A0[4], B0[4], A1[4], B1[4];   // ping-pong groups of 4 nodes

#define LDGROUP(AR, BR, BASE) do {                                             \
    _Pragma("unroll")                                                          \
    for (int s_ = 0; s_ < 4; s_++) {                                           \
        int idx_ = (BASE) + s_;                                                \
        if (idx_ < i1) {                                                       \
            const float4* rp_ = (const float4*)(xf + (size_t)idx_ * DD);       \
            AR[s_] = rp_[lane]; BR[s_] = rp_[32 + lane];                       \
        } else {                                                               \
            AR[s_] = make_float4(0.f, 0.f, 0.f, 0.f);                          \
            BR[s_] = make_float4(0.f, 0.f, 0.f, 0.f);                          \
        }                                                                      \
    } } while (0)

    auto process = [&](const float4* a, const float4* b, int base) {
        float lg = b2v;
#pragma unroll
        for (int j = 0; j < DL; j++) {
            float4 w0 = *(const float4*)&Ws[j][lane * 4];
            float4 w1 = *(const float4*)&Ws[j][128 + lane * 4];
            float pA, pB, pC, pD;
            {   float s;
                s = w0.x * a[0].x; s = fmaf(w0.y, a[0].y, s); s = fmaf(w0.z, a[0].z, s); s = fmaf(w0.w, a[0].w, s);
                s = fmaf(w1.x, b[0].x, s); s = fmaf(w1.y, b[0].y, s); s = fmaf(w1.z, b[0].z, s); s = fmaf(w1.w, b[0].w, s);
                pA = s;
                s = w0.x * a[1].x; s = fmaf(w0.y, a[1].y, s); s = fmaf(w0.z, a[1].z, s); s = fmaf(w0.w, a[1].w, s);
                s = fmaf(w1.x, b[1].x, s); s = fmaf(w1.y, b[1].y, s); s = fmaf(w1.z, b[1].z, s); s = fmaf(w1.w, b[1].w, s);
                pB = s;
                s = w0.x * a[2].x; s = fmaf(w0.y, a[2].y, s); s = fmaf(w0.z, a[2].z, s); s = fmaf(w0.w, a[2].w, s);
                s = fmaf(w1.x, b[2].x, s); s = fmaf(w1.y, b[2].y, s); s = fmaf(w1.z, b[2].z, s); s = fmaf(w1.w, b[2].w, s);
                pC = s;
                s = w0.x * a[3].x; s = fmaf(w0.y, a[3].y, s); s = fmaf(w0.z, a[3].z, s); s = fmaf(w0.w, a[3].w, s);
                s = fmaf(w1.x, b[3].x, s); s = fmaf(w1.y, b[3].y, s); s = fmaf(w1.z, b[3].z, s); s = fmaf(w1.w, b[3].w, s);
                pD = s;
            }
            // round xor16 per node, then select A|B and C|D
            float ra = pA + __shfl_xor_sync(0xffffffffu, pA, 16);
            float rb = pB + __shfl_xor_sync(0xffffffffu, pB, 16);
            float rc = pC + __shfl_xor_sync(0xffffffffu, pC, 16);
            float rd = pD + __shfl_xor_sync(0xffffffffu, pD, 16);
            float v1 = (lane & 16) ? rb : ra;
            float v2 = (lane & 16) ? rd : rc;
            v1 += __shfl_xor_sync(0xffffffffu, v1, 8);
            v2 += __shfl_xor_sync(0xffffffffu, v2, 8);
            float v = (lane & 8) ? v2 : v1;
            v += __shfl_xor_sync(0xffffffffu, v, 4);
            v += __shfl_xor_sync(0xffffffffu, v, 2);
            v += __shfl_xor_sync(0xffffffffu, v, 1);
            // v is the full p-sum for this lane's node (by nsel)
            float h = c1r[j] + v;
            h = (h > 0.f) ? h : 0.01f * h;
            lg = fmaf(w2r[j], h, lg);
        }
        lg = (lg > 0.f) ? lg : 0.01f * lg;
        float w = (base + nsel < i1) ? __expf(lg) : 0.f;   // logits O(0.2): no max-sub
        float wA = __shfl_sync(0xffffffffu, w, 0);
        float wB = __shfl_sync(0xffffffffu, w, 16);
        float wC = __shfl_sync(0xffffffffu, w, 8);
        float wD = __shfl_sync(0xffffffffu, w, 24);
        Z += (wA + wB) + (wC + wD);
        acc0 = fmaf(wA, a[0].x, acc0); acc0 = fmaf(wB, a[1].x, acc0); acc0 = fmaf(wC, a[2].x, acc0); acc0 = fmaf(wD, a[3].x, acc0);
        acc1 = fmaf(wA, a[0].y, acc1); acc1 = fmaf(wB, a[1].y, acc1); acc1 = fmaf(wC, a[2].y, acc1); acc1 = fmaf(wD, a[3].y, acc1);
        acc2 = fmaf(wA, a[0].z, acc2); acc2 = fmaf(wB, a[1].z, acc2); acc2 = fmaf(wC, a[2].z, acc2); acc2 = fmaf(wD, a[3].z, acc2);
        acc3 = fmaf(wA, a[0].w, acc3); acc3 = fmaf(wB, a[1].w, acc3); acc3 = fmaf(wC, a[2].w, acc3); acc3 = fmaf(wD, a[3].w, acc3);
        acc4 = fmaf(wA, b[0].x, acc4); acc4 = fmaf(wB, b[1].x, acc4); acc4 = fmaf(wC, b[2].x, acc4); acc4 = fmaf(wD, b[3].x, acc4);
        acc5 = fmaf(wA, b[0].y, acc5); acc5 = fmaf(wB, b[1].y, acc5); acc5 = fmaf(wC, b[2].y, acc5); acc5 = fmaf(wD, b[3].y, acc5);
        acc6 = fmaf(wA, b[0].z, acc6); acc6 = fmaf(wB, b[1].z, acc6); acc6 = fmaf(wC, b[2].z, acc6); acc6 = fmaf(wD, b[3].z, acc6);
        acc7 = fmaf(wA, b[0].w, acc7); acc7 = fmaf(wB, b[1].w, acc7); acc7 = fmaf(wC, b[2].w, acc7); acc7 = fmaf(wD, b[3].w, acc7);
    };

    int bgrp = i0 + wo * 4;                // this warp's first group; stride 16
    if (bgrp < i1) {
        LDGROUP(A0, B0, bgrp);
        int b = bgrp;
        while (true) {
            if (b + 16 < i1) LDGROUP(A1, B1, b + 16);
            process(A0, B0, b);
            b += 16;
            if (b >= i1) break;
            if (b + 16 < i1) LDGROUP(A0, B0, b + 16);
            process(A1, B1, b);
            b += 16;
            if (b >= i1) break;
        }
    }
#undef LDGROUP

    // combine 4 warps
    if (lane == 0) s_Z[wo] = Z;
    s_acc[wo][lane]      = make_float4(acc0, acc1, acc2, acc3);
    s_acc[wo][32 + lane] = make_float4(acc4, acc5, acc6, acc7);
    __syncthreads();
    if (tid < 64) {
        float Zt = s_Z[0] + s_Z[1] + s_Z[2] + s_Z[3];
        float invZ = (i1 > i0) ? (1.f / Zt) : 0.f;
        float4 v0 = s_acc[0][tid], v1 = s_acc[1][tid], v2 = s_acc[2][tid], v3 = s_acc[3][tid];
        float4 o;
        o.x = (v0.x + v1.x + v2.x + v3.x) * invZ;
        o.y = (v0.y + v1.y + v2.y + v3.y) * invZ;
        o.z = (v0.z + v1.z + v2.z + v3.z) * invZ;
        o.w = (v0.w + v1.w + v2.w + v3.w) * invZ;
        ((float4*)(d_Sdiv + (size_t)g * DD))[tid] = o;
        if (tid == 0) d_has[g] = (i1 > i0) ? 1.f : 0.f;
    }
}

// ---------------- K5: SGEMM  C[4096x768] = A[4096x256] * B[768x256]^T + bias ----------------
// 128x128 tile, 8x8 per thread, 256 threads.
// mode 0: A=d_Sdiv, B=d_Wcomb, C=d_gi, bias = b_ih + has[m]*bmsg_ih
// mode 1: A=graph_feats, B=W_hh,  C=d_gh, bias = b_hh
__global__ void __launch_bounds__(256) k_gemm(int mode, const float* __restrict__ Aparam,
                                              const float* __restrict__ Bparam,
                                              const float* __restrict__ bias) {
    const float* A  = mode ? Aparam : d_Sdiv;
    const float* Bw = mode ? Bparam : d_Wcomb;
    float* C = mode ? d_gh : d_gi;

    __shared__ float As[8][128];
    __shared__ float Bs[8][128];
    int bm = blockIdx.y * 128, bn = blockIdx.x * 128;
    int tid = threadIdx.x;
    int lr = tid >> 1, lc = (tid & 1) * 4;   // load: 128 rows x 8 k
    int tx = tid & 15, ty = tid >> 4;        // 16x16 threads, 8x8 each

    float acc[8][8];
#pragma unroll
    for (int i = 0; i < 8; i++)
#pragma unroll
        for (int j = 0; j < 8; j++) acc[i][j] = 0.f;

    float4 av = *(const float4*)(A + (size_t)(bm + lr) * DD + lc);
    float4 bv = *(const float4*)(Bw + (size_t)(bn + lr) * DD + lc);

    for (int k0 = 0; k0 < DD; k0 += 8) {
        As[lc + 0][lr] = av.x; As[lc + 1][lr] = av.y;
        As[lc + 2][lr] = av.z; As[lc + 3][lr] = av.w;
        Bs[lc + 0][lr] = bv.x; Bs[lc + 1][lr] = bv.y;
        Bs[lc + 2][lr] = bv.z; Bs[lc + 3][lr] = bv.w;
        __syncthreads();
        if (k0 + 8 < DD) {
            av = *(const float4*)(A + (size_t)(bm + lr) * DD + k0 + 8 + lc);
            bv = *(const float4*)(Bw + (size_t)(bn + lr) * DD + k0 + 8 + lc);
        }
#pragma unroll
        for (int k = 0; k < 8; k++) {
            float ar[8], br[8];
            *(float4*)(ar)     = *(const float4*)&As[k][ty * 4];
            *(float4*)(ar + 4) = *(const float4*)&As[k][64 + ty * 4];
            *(float4*)(br)     = *(const float4*)&Bs[k][tx * 4];
            *(float4*)(br + 4) = *(const float4*)&Bs[k][64 + tx * 4];
#pragma unroll
            for (int i = 0; i < 8; i++)
#pragma unroll
                for (int j = 0; j < 8; j++) acc[i][j] = fmaf(ar[i], br[j], acc[i][j]);
        }
        __syncthreads();
    }

#pragma unroll
    for (int i = 0; i < 8; i++) {
        int m = bm + ((i < 4) ? (ty * 4 + i) : (64 + ty * 4 + (i - 4)));
        float hv = mode ? 0.f : d_has[m];
#pragma unroll
        for (int jh = 0; jh < 2; jh++) {
            int n0 = bn + jh * 64 + tx * 4;
            float4 o;
            o.x = acc[i][jh * 4 + 0] + bias[n0 + 0] + (mode ? 0.f : hv * d_bmsgih[n0 + 0]);
            o.y = acc[i][jh * 4 + 1] + bias[n0 + 1] + (mode ? 0.f : hv * d_bmsgih[n0 + 1]);
            o.z = acc[i][jh * 4 + 2] + bias[n0 + 2] + (mode ? 0.f : hv * d_bmsgih[n0 + 2]);
            o.w = acc[i][jh * 4 + 3] + bias[n0 + 3] + (mode ? 0.f : hv * d_bmsgih[n0 + 3]);
            *(float4*)(C + (size_t)m * TH + n0) = o;
        }
    }
}

// ---------------- K6: GRU gate combine (float4) ----------------
__global__ void k_gates(const float* __restrict__ gf, float* __restrict__ out) {
    int idx = blockIdx.x * blockDim.x + threadIdx.x;   // over BB*DD/4
    int g = idx >> 6, f4 = idx & 63;
    const float4* gi = (const float4*)(d_gi + (size_t)g * TH);
    const float4* gh = (const float4*)(d_gh + (size_t)g * TH);
    float4 ir = gi[f4],      iz = gi[64 + f4],  in_ = gi[128 + f4];
    float4 hr = gh[f4],      hz = gh[64 + f4],  hn  = gh[128 + f4];
    float4 gfv = ((const float4*)gf)[idx];
    float4 o;
    {
        float r = 1.f / (1.f + __expf(-(ir.x + hr.x)));
        float z = 1.f / (1.f + __expf(-(iz.x + hz.x)));
        float n = tanhf(in_.x + r * hn.x);
        o.x = (1.f - z) * n + z * gfv.x;
    }
    {
        float r = 1.f / (1.f + __expf(-(ir.y + hr.y)));
        float z = 1.f / (1.f + __expf(-(iz.y + hz.y)));
        float n = tanhf(in_.y + r * hn.y);
        o.y = (1.f - z) * n + z * gfv.y;
    }
    {
        float r = 1.f / (1.f + __expf(-(ir.z + hr.z)));
        float z = 1.f / (1.f + __expf(-(iz.z + hz.z)));
        float n = tanhf(in_.z + r * hn.z);
        o.z = (1.f - z) * n + z * gfv.z;
    }
    {
        float r = 1.f / (1.f + __expf(-(ir.w + hr.w)));
        float z = 1.f / (1.f + __expf(-(iz.w + hz.w)));
        float n = tanhf(in_.w + r * hn.w);
        o.w = (1.f - z) * n + z * gfv.w;
    }
    ((float4*)out)[idx] = o;
}

// ---------------- launch ----------------
extern "C" void kernel_launch(void* const* d_in, const int* in_sizes, int n_in,
                              void* d_out, int out_size) {
    const float* node = (const float*)d_in[0];
    const float* gf   = (const float*)d_in[1];
    const int*   seg  = (const int*)d_in[2];     // JAX coerces int64 -> int32 (x64 disabled)
    const float* Wmsg = (const float*)d_in[3];
    const float* bmsg = (const float*)d_in[4];
    const float* Wl1  = (const float*)d_in[5];
    const float* bl1  = (const float*)d_in[6];
    const float* Wl2  = (const float*)d_in[7];
    const float* bl2  = (const float*)d_in[8];
    const float* Wih  = (const float*)d_in[9];
    const float* Whh  = (const float*)d_in[10];
    const float* bih  = (const float*)d_in[11];
    const float* bhh  = (const float*)d_in[12];
    float* out = (float*)d_out;

    k_segstart<<<(BB + 1 + 255) / 256, 256>>>(seg);
    k_c1<<<BB, 256>>>(gf, Wl1, bl1);
    k_wcomb<<<TH / 4, 256>>>(Wih, Wmsg);
    k_bmsgih<<<TH, 256>>>(Wih, bmsg);
    k_attn<<<BB, 128>>>(node, Wl1, Wl2, bl2);
    dim3 gg(TH / 128, BB / 128);
    k_gemm<<<gg, 256>>>(0, nullptr, nullptr, bih);
    k_gemm<<<gg, 256>>>(1, gf, Whh, bhh);
    k_gates<<<(BB * DD / 4) / 256, 256>>>(gf, out);
}